// round 1
// baseline (speedup 1.0000x reference)
#include <cuda_runtime.h>
#include <cuda_bf16.h>

// ThermoQuantizer: groupwise abs-mean scale + soft (softmax) quantization onto a
// uniform 16-level codebook + lerp.
//
// Math restructure (uniform codebook c_k = c0 + k*D):
//   p_k ∝ exp(-(xn - c_k)^2 / T)  ∝  R^k * G_k,
//   R = exp(2*D*xn/T)  (ONE exp per element),  G_k = exp(-c_k^2/T) (block consts)
//   qxn = (Σ G_k c_k R^k) / (Σ G_k R^k)   -- two degree-15 Horner chains,
// packed as (den,num) pairs into fma.rn.f32x2 (FFMA2): 15 packed FMA / element.
//
// Mapping: 1 warp = 1 group of 128 elements (float4 per thread), warp-shfl
// reduction for the group abs-mean. Fully coalesced 128B-sector loads/stores.

#define FULL_MASK 0xFFFFFFFFu

__device__ __forceinline__ unsigned long long pk2(float lo, float hi) {
    unsigned long long r;
    asm("mov.b64 %0, {%1, %2};" : "=l"(r) : "f"(lo), "f"(hi));
    return r;
}

__device__ __forceinline__ void upk2(unsigned long long v, float& lo, float& hi) {
    asm("mov.b64 {%0, %1}, %2;" : "=f"(lo), "=f"(hi) : "l"(v));
}

// Packed dual-FMA: d.lo = a.lo*b.lo + c.lo ; d.hi = a.hi*b.hi + c.hi
__device__ __forceinline__ unsigned long long fma2(unsigned long long a,
                                                   unsigned long long b,
                                                   unsigned long long c) {
    unsigned long long d;
    asm("fma.rn.f32x2 %0, %1, %2, %3;" : "=l"(d) : "l"(a), "l"(b), "l"(c));
    return d;
}

__device__ __forceinline__ float ex2_approx(float a) {
    float r;
    asm("ex2.approx.ftz.f32 %0, %1;" : "=f"(r) : "f"(a));
    return r;
}

__global__ __launch_bounds__(256) void ThermoQuantizer_50122268345057_kernel(
    const float* __restrict__ x,
    const float* __restrict__ cb,
    const float* __restrict__ p_pressure,
    const float* __restrict__ p_temp,
    float* __restrict__ out,
    int n4)   // number of float4 quads = total_elems / 4 (divisible by 32)
{
    __shared__ unsigned long long sC[16];   // packed (G_k, G_k * c_k)

    const float temp = p_temp[0] + 1e-6f;
    const float invT = 1.0f / temp;

    const int tid = threadIdx.x;
    if (tid < 16) {
        float c = cb[tid];
        float g = __expf(-c * c * invT);
        sC[tid] = pk2(g, g * c);
    }
    __syncthreads();

    const int gi = blockIdx.x * blockDim.x + tid;
    if (gi >= n4) return;   // whole warps only (n4 % 32 == 0), shfl stays safe

    const float pressure = p_pressure[0];
    const float d01 = cb[1] - cb[0];   // uniform codebook spacing D
    // R = exp(2*D*xn/T) = 2^(xn * K2), K2 = 2*D/T * log2(e)
    const float K2 = 2.0f * d01 * invT * 1.4426950408889634f;

    // Load coefficients into registers once (16 x LDS.64)
    unsigned long long C[16];
    #pragma unroll
    for (int k = 0; k < 16; ++k) C[k] = sC[k];

    const float4 v = reinterpret_cast<const float4*>(x)[gi];

    // --- group abs-mean (warp = group of 128) ---
    float s = fabsf(v.x) + fabsf(v.y) + fabsf(v.z) + fabsf(v.w);
    #pragma unroll
    for (int o = 16; o > 0; o >>= 1) s += __shfl_xor_sync(FULL_MASK, s, o);
    const float mean_c = fmaxf(s * (1.0f / 128.0f), 1e-5f);  // clip(mean, 1e-5)
    const float kk = K2 / mean_c;   // xn*K2 = x * (K2/mean)  (scale = 1/mean_c)

    float xs[4] = {v.x, v.y, v.z, v.w};

    // --- per-element R = 2^(clamp(x*kk)) ---
    unsigned long long R2[4], acc[4];
    #pragma unroll
    for (int e = 0; e < 4; ++e) {
        float a = xs[e] * kk;
        // clamp: R^15 <= 2^120 (no overflow); saturation only where the softmax
        // is already pinned to an end code, so the result is unchanged.
        a = fminf(fmaxf(a, -8.0f), 8.0f);
        float r = ex2_approx(a);
        R2[e] = pk2(r, r);
        acc[e] = C[15];
    }

    // --- dual Horner (den in .lo, num in .hi), 4 independent chains for ILP ---
    #pragma unroll
    for (int k = 14; k >= 0; --k) {
        const unsigned long long ck = C[k];
        #pragma unroll
        for (int e = 0; e < 4; ++e) acc[e] = fma2(acc[e], R2[e], ck);
    }

    // --- epilogue: qxn = num/den ; qx = qxn*mean ; out = x + p*(qx - x) ---
    float res[4];
    #pragma unroll
    for (int e = 0; e < 4; ++e) {
        float den, num;
        upk2(acc[e], den, num);
        float qxn = __fdividef(num, den);
        float qx  = qxn * mean_c;
        res[e] = fmaf(pressure, qx - xs[e], xs[e]);
    }

    float4 o4;
    o4.x = res[0]; o4.y = res[1]; o4.z = res[2]; o4.w = res[3];
    reinterpret_cast<float4*>(out)[gi] = o4;
}

extern "C" void kernel_launch(void* const* d_in, const int* in_sizes, int n_in,
                              void* d_out, int out_size) {
    const float* x  = (const float*)d_in[0];
    const float* cb = (const float*)d_in[1];
    const float* pr = (const float*)d_in[2];
    const float* tp = (const float*)d_in[3];
    float* out = (float*)d_out;

    const int n4 = out_size / 4;           // 4M quads for 4096x4096
    const int threads = 256;
    const int blocks = (n4 + threads - 1) / threads;
    ThermoQuantizer_50122268345057_kernel<<<blocks, threads>>>(x, cb, pr, tp, out, n4);
}

// round 2
// speedup vs baseline: 1.2889x; 1.2889x over previous
#include <cuda_runtime.h>
#include <cuda_bf16.h>

// ThermoQuantizer: groupwise abs-mean scale + soft (softmax) quantization onto a
// uniform 16-level codebook + lerp.
//
// Math (uniform codebook c_k = c0 + k*D):
//   p_k ∝ exp(-(xn-c_k)^2/T) ∝ G_k * R^k,  R = 2^(xn*K2), K2 = 2D/T*log2(e),
//   G_k = exp(-c_k^2/T)  (block constants).
//   qxn = (Σ G_k c_k R^k)/(Σ G_k R^k): two degree-15 Horner chains packed as
//   (den,num) into fma.rn.f32x2 -> 15 packed FMA per element.
//
// Mapping (R2): 1 warp = 2 groups (half-warp per group), 8 elements/thread
// (2x float4). Group abs-mean via 4-stage butterfly SHFL confined to each
// 16-lane half. All per-thread fixed costs amortized over 8 outputs.

#define FULL_MASK 0xFFFFFFFFu

__device__ __forceinline__ unsigned long long pk2(float lo, float hi) {
    unsigned long long r;
    asm("mov.b64 %0, {%1, %2};" : "=l"(r) : "f"(lo), "f"(hi));
    return r;
}

__device__ __forceinline__ void upk2(unsigned long long v, float& lo, float& hi) {
    asm("mov.b64 {%0, %1}, %2;" : "=f"(lo), "=f"(hi) : "l"(v));
}

// Packed dual-FMA: d.lo = a.lo*b.lo + c.lo ; d.hi = a.hi*b.hi + c.hi
__device__ __forceinline__ unsigned long long fma2(unsigned long long a,
                                                   unsigned long long b,
                                                   unsigned long long c) {
    unsigned long long d;
    asm("fma.rn.f32x2 %0, %1, %2, %3;" : "=l"(d) : "l"(a), "l"(b), "l"(c));
    return d;
}

__device__ __forceinline__ float ex2_approx(float a) {
    float r;
    asm("ex2.approx.ftz.f32 %0, %1;" : "=f"(r) : "f"(a));
    return r;
}

__global__ __launch_bounds__(256) void ThermoQuantizer_50122268345057_kernel(
    const float* __restrict__ x,
    const float* __restrict__ cb,
    const float* __restrict__ p_pressure,
    const float* __restrict__ p_temp,
    float* __restrict__ out,
    int n4)   // total float4 quads
{
    __shared__ unsigned long long sC[16];   // packed (G_k, G_k * c_k)
    __shared__ float sK2, sPres;

    const int tid = threadIdx.x;
    if (tid < 16) {
        const float invT = 1.0f / (p_temp[0] + 1e-6f);
        float c = cb[tid];
        float g = __expf(-c * c * invT);
        sC[tid] = pk2(g, g * c);
        if (tid == 0) {
            sK2 = 2.0f * (cb[1] - cb[0]) * invT * 1.4426950408889634f;
            sPres = p_pressure[0];
        }
    }
    __syncthreads();

    const int lane = tid & 31;
    const int h = lane >> 4;            // which of the warp's 2 groups
    const int q = lane & 15;            // lane within half-warp
    const int warpGlobal = blockIdx.x * (blockDim.x >> 5) + (tid >> 5);
    // warp covers 64 quads (= 2 groups of 32 quads). Half h starts at +32*h.
    const int quadBase = warpGlobal * 64 + h * 32 + q;
    const bool valid = (quadBase + 16) < n4;   // groups are whole or absent

    float4 v0, v1;
    if (valid) {
        v0 = reinterpret_cast<const float4*>(x)[quadBase];
        v1 = reinterpret_cast<const float4*>(x)[quadBase + 16];
    } else {
        v0 = make_float4(0.f, 0.f, 0.f, 0.f);
        v1 = v0;
    }

    // --- group abs-mean over this 16-lane half (128 elements) ---
    float s = (fabsf(v0.x) + fabsf(v0.y)) + (fabsf(v0.z) + fabsf(v0.w))
            + (fabsf(v1.x) + fabsf(v1.y)) + (fabsf(v1.z) + fabsf(v1.w));
    #pragma unroll
    for (int o = 8; o > 0; o >>= 1) s += __shfl_xor_sync(FULL_MASK, s, o);
    const float mean_c = fmaxf(s * (1.0f / 128.0f), 1e-5f);
    const float kk = __fdividef(sK2, mean_c);   // xn*K2 = x*(K2/mean)

    float xs[8] = {v0.x, v0.y, v0.z, v0.w, v1.x, v1.y, v1.z, v1.w};

    // --- per-element R = 2^(clamp(x*kk, +-8)); R^15 <= 2^120, no overflow.
    //     Clamp engages only where the softmax is pinned to an end code. ---
    unsigned long long R2[8], acc[8];
    const unsigned long long c15 = sC[15];
    #pragma unroll
    for (int e = 0; e < 8; ++e) {
        float a = xs[e] * kk;
        a = fminf(fmaxf(a, -8.0f), 8.0f);
        float r = ex2_approx(a);
        R2[e] = pk2(r, r);
        acc[e] = c15;
    }

    // --- dual Horner (den=.lo, num=.hi), 8 independent chains for ILP ---
    #pragma unroll
    for (int k = 14; k >= 0; --k) {
        const unsigned long long ck = sC[k];
        #pragma unroll
        for (int e = 0; e < 8; ++e) acc[e] = fma2(acc[e], R2[e], ck);
    }

    // --- epilogue: qxn = num/den; qx = qxn*mean; out = x + p*(qx - x) ---
    const float pres = sPres;
    float res[8];
    #pragma unroll
    for (int e = 0; e < 8; ++e) {
        float den, num;
        upk2(acc[e], den, num);
        float qxn = __fdividef(num, den);
        float d   = fmaf(qxn, mean_c, -xs[e]);   // qx - x
        res[e] = fmaf(pres, d, xs[e]);
    }

    if (valid) {
        float4 o0, o1;
        o0.x = res[0]; o0.y = res[1]; o0.z = res[2]; o0.w = res[3];
        o1.x = res[4]; o1.y = res[5]; o1.z = res[6]; o1.w = res[7];
        reinterpret_cast<float4*>(out)[quadBase]      = o0;
        reinterpret_cast<float4*>(out)[quadBase + 16] = o1;
    }
}

extern "C" void kernel_launch(void* const* d_in, const int* in_sizes, int n_in,
                              void* d_out, int out_size) {
    const float* x  = (const float*)d_in[0];
    const float* cb = (const float*)d_in[1];
    const float* pr = (const float*)d_in[2];
    const float* tp = (const float*)d_in[3];
    float* out = (float*)d_out;

    const int n4 = out_size / 4;                 // quads
    const int quadsPerBlock = 8 * 64;            // 8 warps * 64 quads
    const int blocks = (n4 + quadsPerBlock - 1) / quadsPerBlock;
    ThermoQuantizer_50122268345057_kernel<<<blocks, 256>>>(x, cb, pr, tp, out, n4);
}